// round 1
// baseline (speedup 1.0000x reference)
#include <cuda_runtime.h>
#include <math.h>

#define N_IMG 2
#define CCH   256
#define HH    256
#define WW    256
#define PHB   7
#define PWB   7
#define NROIS 1024
#define SCALE 0.25f

// 128 MB static scratch for NHWC-transposed features (allowed: __device__ global)
__device__ float g_nhwc[(size_t)N_IMG * HH * WW * CCH];

// ---------------------------------------------------------------------------
// Kernel 1: NCHW -> NHWC transpose. Per image: matrix [C][H*W] -> [H*W][C].
// 32x32 tiles via padded smem; both gmem reads and writes fully coalesced.
// ---------------------------------------------------------------------------
__global__ void __launch_bounds__(256) nchw_to_nhwc_kernel(const float* __restrict__ in)
{
    __shared__ float tile[32][33];
    const int n   = blockIdx.z;
    const int hw0 = blockIdx.x * 32;
    const int c0  = blockIdx.y * 32;
    const int tx  = threadIdx.x;   // 0..31
    const int ty  = threadIdx.y;   // 0..7

    const float* src = in     + (size_t)n * CCH * HH * WW;
    float*       dst = g_nhwc + (size_t)n * HH * WW * CCH;

#pragma unroll
    for (int i = 0; i < 32; i += 8) {
        tile[ty + i][tx] = src[(size_t)(c0 + ty + i) * (HH * WW) + hw0 + tx];
    }
    __syncthreads();
#pragma unroll
    for (int i = 0; i < 32; i += 8) {
        dst[(size_t)(hw0 + ty + i) * CCH + c0 + tx] = tile[tx][ty + i];
    }
}

// ---------------------------------------------------------------------------
// Kernel 2: rotated RoIAlign gather on NHWC features.
// One block per roi, 256 threads (thread = channel). All coordinate math is
// warp-uniform. Each corner read by a warp is one dense 128B line.
// Results staged in smem (stride-49 per thread: conflict-free, 49 coprime 32)
// then flushed with fully coalesced linear stores.
// ---------------------------------------------------------------------------
__global__ void __launch_bounds__(256) roialign_rot_kernel(
    const float* __restrict__ rois, float* __restrict__ out)
{
    extern __shared__ float s_out[];  // CCH * 49 floats = 50176 B
    const int roi = blockIdx.x;
    const int c   = threadIdx.x;

    const float* r = rois + roi * 6;
    const int   b  = (int)r[0];
    const float cx = r[1] * SCALE - 0.5f;
    const float cy = r[2] * SCALE - 0.5f;
    const float rw = r[3] * SCALE;
    const float rh = r[4] * SCALE;
    const float th = r[5];

    float sn, cs;
    sincosf(th, &sn, &cs);

    const float bin_h = rh * (1.0f / PHB);
    const float bin_w = rw * (1.0f / PWB);
    const float y0 = -0.5f * rh;
    const float x0 = -0.5f * rw;

    const float* __restrict__ feat = g_nhwc + (size_t)b * HH * WW * CCH;

    for (int bin = 0; bin < PHB * PWB; ++bin) {
        const int ph = bin / PWB;
        const int pw = bin % PWB;
        float acc = 0.0f;

#pragma unroll
        for (int s = 0; s < 4; ++s) {
            const int iy = s >> 1;
            const int ix = s & 1;
            // sample offsets: (idx + (sub+0.5)/2) * bin
            const float yy = y0 + ((float)ph + ((float)iy + 0.5f) * 0.5f) * bin_h;
            const float xx = x0 + ((float)pw + ((float)ix + 0.5f) * 0.5f) * bin_w;
            float y = yy * cs - xx * sn + cy;
            float x = yy * sn + xx * cs + cx;

            const bool valid = (y > -1.0f) && (y < (float)HH) &&
                               (x > -1.0f) && (x < (float)WW);
            y = fmaxf(y, 0.0f);
            x = fmaxf(x, 0.0f);

            int yl = (int)y;
            int xl = (int)x;
            int yh, xh;
            float ly, lx;
            if (yl >= HH - 1) { yl = HH - 1; yh = HH - 1; ly = 0.0f; }
            else              { yh = yl + 1; ly = y - (float)yl; }
            if (xl >= WW - 1) { xl = WW - 1; xh = WW - 1; lx = 0.0f; }
            else              { xh = xl + 1; lx = x - (float)xl; }
            const float hy = 1.0f - ly;
            const float hx = 1.0f - lx;

            if (valid) {  // warp-uniform branch
                const float* p0 = feat + (size_t)(yl * WW) * CCH;
                const float* p1 = feat + (size_t)(yh * WW) * CCH;
                const float v00 = __ldg(p0 + xl * CCH + c);
                const float v01 = __ldg(p0 + xh * CCH + c);
                const float v10 = __ldg(p1 + xl * CCH + c);
                const float v11 = __ldg(p1 + xh * CCH + c);
                acc += (hy * hx) * v00 + (hy * lx) * v01
                     + (ly * hx) * v10 + (ly * lx) * v11;
            }
        }
        s_out[c * (PHB * PWB) + bin] = acc * 0.25f;
    }

    __syncthreads();
    // out layout (roi, c, ph, pw): roi block owns contiguous CCH*49 floats.
    float* o = out + (size_t)roi * (CCH * PHB * PWB);
    for (int i = c; i < CCH * PHB * PWB; i += 256) {
        o[i] = s_out[i];
    }
}

extern "C" void kernel_launch(void* const* d_in, const int* in_sizes, int n_in,
                              void* d_out, int out_size)
{
    // Identify inputs robustly by size.
    const float* feat = (const float*)d_in[0];
    const float* rois = (const float*)d_in[1];
    if (in_sizes[0] == NROIS * 6) {
        rois = (const float*)d_in[0];
        feat = (const float*)d_in[1];
    }
    float* out = (float*)d_out;

    // Allow 49 KB dynamic smem for the gather kernel (idempotent, capture-safe).
    cudaFuncSetAttribute(roialign_rot_kernel,
                         cudaFuncAttributeMaxDynamicSharedMemorySize,
                         CCH * PHB * PWB * (int)sizeof(float));

    // Kernel 1: transpose to NHWC scratch.
    dim3 tb(32, 8, 1);
    dim3 tg((HH * WW) / 32, CCH / 32, N_IMG);
    nchw_to_nhwc_kernel<<<tg, tb>>>(feat);

    // Kernel 2: gather.
    roialign_rot_kernel<<<NROIS, 256, CCH * PHB * PWB * (int)sizeof(float)>>>(rois, out);
}

// round 2
// speedup vs baseline: 1.8219x; 1.8219x over previous
#include <cuda_runtime.h>
#include <math.h>

#define N_IMG 2
#define CCH   256
#define HH    256
#define WW    256
#define PHB   7
#define PWB   7
#define NBINS (PHB * PWB)
#define NROIS 1024
#define SCALE 0.25f

// 128 MB static scratch for NHWC-transposed features
__device__ float g_nhwc[(size_t)N_IMG * HH * WW * CCH];

// ---------------------------------------------------------------------------
// Kernel 1: NCHW -> NHWC transpose, fully vectorized (LDG.128/STG.128 both
// sides). Tile = 32 channels x 128 hw. Each thread loads a 4c x 4hw block as
// 4 float4s (along hw), transposes in registers, writes 4 float4s (along c)
// to XOR-swizzled smem (conflict-free), then the block flushes coalesced
// float4s to NHWC.
// ---------------------------------------------------------------------------
__global__ void __launch_bounds__(256) nchw_to_nhwc_kernel(const float* __restrict__ in)
{
    __shared__ float4 tile[128 * 8];   // [hw 0..127][c4 0..7], swizzled
    const int n   = blockIdx.z;
    const int hw0 = blockIdx.x * 128;
    const int c0  = blockIdx.y * 32;
    const int t   = threadIdx.x;

    const float* src = in     + (size_t)n * CCH * HH * WW;
    float*       dst = g_nhwc + (size_t)n * HH * WW * CCH;

    const int hw4 = t & 31;    // which float4 along hw (0..31)
    const int c4w = t >> 5;    // which 4-channel group (0..7)

    // Load 4 rows (channels c0+4*c4w+j) of one float4 column each.
    float vv[4][4];
#pragma unroll
    for (int j = 0; j < 4; ++j) {
        float4 ld = *(const float4*)(src + (size_t)(c0 + c4w * 4 + j) * (HH * WW)
                                         + hw0 + hw4 * 4);
        vv[j][0] = ld.x; vv[j][1] = ld.y; vv[j][2] = ld.z; vv[j][3] = ld.w;
    }

    // Register transpose: emit float4 along c for each of the 4 hw rows.
#pragma unroll
    for (int r = 0; r < 4; ++r) {
        float4 o = make_float4(vv[0][r], vv[1][r], vv[2][r], vv[3][r]);
        const int hw = hw4 * 4 + r;
        tile[hw * 8 + (c4w ^ ((hw >> 2) & 7))] = o;   // swizzle: conflict-free
    }
    __syncthreads();

    // Coalesced flush: warp covers 4 hw rows x 8 c-float4 = 4 x 128B segments.
#pragma unroll
    for (int k = 0; k < 4; ++k) {
        const int idx = t + k * 256;           // 0..1023
        const int hw  = idx >> 3;
        const int c4  = idx & 7;
        float4 f = tile[hw * 8 + (c4 ^ ((hw >> 2) & 7))];
        *(float4*)(dst + (size_t)(hw0 + hw) * CCH + c0 + c4 * 4) = f;
    }
}

// ---------------------------------------------------------------------------
// Kernel 2: rotated RoIAlign gather on NHWC features.
// Block = 1 roi, 256 threads = 64 channel-groups (float4) x 4 bin-slices.
// Per bin: compute 8 addresses + weights (branch-free; invalid samples get
// zero weights), issue 8 unconditional LDG.128, then FMA-reduce. Two such
// sample-pair phases per bin. Results staged in smem, flushed as float4.
// ---------------------------------------------------------------------------
__global__ void __launch_bounds__(256) roialign_rot_kernel(
    const float* __restrict__ rois, float* __restrict__ out)
{
    extern __shared__ float s_out[];   // CCH * 49 floats = 50176 B
    const int roi    = blockIdx.x;
    const int tid    = threadIdx.x;
    const int cgrp   = tid & 63;       // float4 channel group (channels 4*cgrp..+3)
    const int bslice = tid >> 6;       // 0..3

    const float* r = rois + roi * 6;
    const int   b  = (int)r[0];
    const float cx = fmaf(r[1], SCALE, -0.5f);
    const float cy = fmaf(r[2], SCALE, -0.5f);
    const float rw = r[3] * SCALE;
    const float rh = r[4] * SCALE;
    float sn, cs;
    sincosf(r[5], &sn, &cs);

    const float bin_h = rh * (1.0f / PHB);
    const float bin_w = rw * (1.0f / PWB);
    const float y0 = -0.5f * rh;
    const float x0 = -0.5f * rw;

    const float4* __restrict__ feat =
        (const float4*)g_nhwc + (size_t)b * (HH * WW * (CCH / 4)) + cgrp;

    for (int bin = bslice; bin < NBINS; bin += 4) {
        const int ph = bin / PWB;
        const int pw = bin - ph * PWB;
        float a0 = 0.f, a1 = 0.f, a2 = 0.f, a3 = 0.f;

#pragma unroll
        for (int sp = 0; sp < 2; ++sp) {          // iy = sp
            int   idx[8];
            float w[8];
            const float yy = y0 + ((float)ph + ((float)sp + 0.5f) * 0.5f) * bin_h;
#pragma unroll
            for (int ix = 0; ix < 2; ++ix) {
                const float xx = x0 + ((float)pw + ((float)ix + 0.5f) * 0.5f) * bin_w;
                float y = yy * cs - xx * sn + cy;
                float x = yy * sn + xx * cs + cx;

                const bool valid = (y > -1.0f) & (y < (float)HH) &
                                   (x > -1.0f) & (x < (float)WW);
                y = fmaxf(y, 0.0f);
                x = fmaxf(x, 0.0f);

                int yl = (int)y;
                int xl = (int)x;
                int yh, xh; float ly, lx;
                if (yl >= HH - 1) { yl = HH - 1; yh = HH - 1; ly = 0.f; }
                else              { yh = yl + 1; ly = y - (float)yl; }
                if (xl >= WW - 1) { xl = WW - 1; xh = WW - 1; lx = 0.f; }
                else              { xh = xl + 1; lx = x - (float)xl; }

                const float vsc = valid ? 0.25f : 0.0f;  // folds the /4 mean
                const float hy = 1.f - ly, hx = 1.f - lx;
                w[ix * 4 + 0] = hy * hx * vsc;
                w[ix * 4 + 1] = hy * lx * vsc;
                w[ix * 4 + 2] = ly * hx * vsc;
                w[ix * 4 + 3] = ly * lx * vsc;

                const int rl = yl * WW, rh2 = yh * WW;
                idx[ix * 4 + 0] = (rl  + xl) << 6;   // * (CCH/4)
                idx[ix * 4 + 1] = (rl  + xh) << 6;
                idx[ix * 4 + 2] = (rh2 + xl) << 6;
                idx[ix * 4 + 3] = (rh2 + xh) << 6;
            }

            // Batched, unconditional loads: 8 x LDG.128 in flight per warp.
            float4 v[8];
#pragma unroll
            for (int i = 0; i < 8; ++i) v[i] = __ldg(feat + idx[i]);
#pragma unroll
            for (int i = 0; i < 8; ++i) {
                a0 = fmaf(w[i], v[i].x, a0);
                a1 = fmaf(w[i], v[i].y, a1);
                a2 = fmaf(w[i], v[i].z, a2);
                a3 = fmaf(w[i], v[i].w, a3);
            }
        }

        const int cb = cgrp * 4;
        s_out[(cb + 0) * NBINS + bin] = a0;
        s_out[(cb + 1) * NBINS + bin] = a1;
        s_out[(cb + 2) * NBINS + bin] = a2;
        s_out[(cb + 3) * NBINS + bin] = a3;
    }

    __syncthreads();
    // Coalesced float4 flush: roi block owns contiguous CCH*49 floats.
    float4* o4 = (float4*)(out + (size_t)roi * (CCH * NBINS));
    const float4* s4 = (const float4*)s_out;
#pragma unroll 4
    for (int i = tid; i < (CCH * NBINS) / 4; i += 256) {
        o4[i] = s4[i];
    }
}

extern "C" void kernel_launch(void* const* d_in, const int* in_sizes, int n_in,
                              void* d_out, int out_size)
{
    const float* feat = (const float*)d_in[0];
    const float* rois = (const float*)d_in[1];
    if (in_sizes[0] == NROIS * 6) {
        rois = (const float*)d_in[0];
        feat = (const float*)d_in[1];
    }
    float* out = (float*)d_out;

    cudaFuncSetAttribute(roialign_rot_kernel,
                         cudaFuncAttributeMaxDynamicSharedMemorySize,
                         CCH * NBINS * (int)sizeof(float));

    dim3 tg((HH * WW) / 128, CCH / 32, N_IMG);
    nchw_to_nhwc_kernel<<<tg, 256>>>(feat);

    roialign_rot_kernel<<<NROIS, 256, CCH * NBINS * (int)sizeof(float)>>>(rois, out);
}

// round 3
// speedup vs baseline: 2.4816x; 1.3620x over previous
#include <cuda_runtime.h>
#include <math.h>

#define N_IMG 2
#define CCH   256
#define HH    256
#define WW    256
#define PHB   7
#define PWB   7
#define NBINS (PHB * PWB)
#define NROIS 1024
#define SCALE 0.25f

// 128 MB static scratch for NHWC-transposed features
__device__ float g_nhwc[(size_t)N_IMG * HH * WW * CCH];

// ---------------------------------------------------------------------------
// Kernel 1: NCHW -> NHWC transpose, fully vectorized (LDG.128/STG.128 both
// sides). Tile = 32 channels x 128 hw, register 4x4 transpose + XOR-swizzled
// smem (conflict-free), coalesced float4 flush.
// ---------------------------------------------------------------------------
__global__ void __launch_bounds__(256) nchw_to_nhwc_kernel(const float* __restrict__ in)
{
    __shared__ float4 tile[128 * 8];   // [hw 0..127][c4 0..7], swizzled
    const int n   = blockIdx.z;
    const int hw0 = blockIdx.x * 128;
    const int c0  = blockIdx.y * 32;
    const int t   = threadIdx.x;

    const float* src = in     + (size_t)n * CCH * HH * WW;
    float*       dst = g_nhwc + (size_t)n * HH * WW * CCH;

    const int hw4 = t & 31;    // float4 column along hw (0..31)
    const int c4w = t >> 5;    // 4-channel group (0..7)

    float vv[4][4];
#pragma unroll
    for (int j = 0; j < 4; ++j) {
        float4 ld = *(const float4*)(src + (size_t)(c0 + c4w * 4 + j) * (HH * WW)
                                         + hw0 + hw4 * 4);
        vv[j][0] = ld.x; vv[j][1] = ld.y; vv[j][2] = ld.z; vv[j][3] = ld.w;
    }
#pragma unroll
    for (int r = 0; r < 4; ++r) {
        float4 o = make_float4(vv[0][r], vv[1][r], vv[2][r], vv[3][r]);
        const int hw = hw4 * 4 + r;
        tile[hw * 8 + (c4w ^ ((hw >> 2) & 7))] = o;
    }
    __syncthreads();
#pragma unroll
    for (int k = 0; k < 4; ++k) {
        const int idx = t + k * 256;
        const int hw  = idx >> 3;
        const int c4  = idx & 7;
        float4 f = tile[hw * 8 + (c4 ^ ((hw >> 2) & 7))];
        *(float4*)(dst + (size_t)(hw0 + hw) * CCH + c0 + c4 * 4) = f;
    }
}

// ---------------------------------------------------------------------------
// Kernel 2: rotated RoIAlign gather on NHWC features.
// Block = 1 roi, 512 threads = 64 channel-groups (float4) x 8 bin-slices.
// Per bin-phase: branch-free weights (invalid samples -> zero weight), 8
// unconditional LDG.128 in flight, then FMA-reduce. smem staging -> fully
// coalesced float4 output flush. Regs capped for 3 blocks/SM (75% occ).
// ---------------------------------------------------------------------------
__global__ void __launch_bounds__(512, 3) roialign_rot_kernel(
    const float* __restrict__ rois, float* __restrict__ out)
{
    extern __shared__ float s_out[];   // CCH * 49 floats = 50176 B
    const int roi    = blockIdx.x;
    const int tid    = threadIdx.x;
    const int cgrp   = tid & 63;       // float4 channel group
    const int bslice = tid >> 6;       // 0..7

    const float* r = rois + roi * 6;
    const int   b  = (int)r[0];
    const float cx = fmaf(r[1], SCALE, -0.5f);
    const float cy = fmaf(r[2], SCALE, -0.5f);
    const float rw = r[3] * SCALE;
    const float rh = r[4] * SCALE;
    float sn, cs;
    sincosf(r[5], &sn, &cs);

    const float bin_h = rh * (1.0f / PHB);
    const float bin_w = rw * (1.0f / PWB);
    const float y0 = -0.5f * rh;
    const float x0 = -0.5f * rw;

    const float4* __restrict__ feat =
        (const float4*)g_nhwc + (size_t)b * (HH * WW * (CCH / 4)) + cgrp;

    for (int bin = bslice; bin < NBINS; bin += 8) {
        const int ph = bin / PWB;
        const int pw = bin - ph * PWB;
        float a0 = 0.f, a1 = 0.f, a2 = 0.f, a3 = 0.f;

#pragma unroll
        for (int sp = 0; sp < 2; ++sp) {          // iy = sp
            int   idx[8];
            float w[8];
            const float yy = y0 + ((float)ph + ((float)sp + 0.5f) * 0.5f) * bin_h;
#pragma unroll
            for (int ix = 0; ix < 2; ++ix) {
                const float xx = x0 + ((float)pw + ((float)ix + 0.5f) * 0.5f) * bin_w;
                float y = yy * cs - xx * sn + cy;
                float x = yy * sn + xx * cs + cx;

                const bool valid = (y > -1.0f) & (y < (float)HH) &
                                   (x > -1.0f) & (x < (float)WW);
                y = fmaxf(y, 0.0f);
                x = fmaxf(x, 0.0f);

                int yl = (int)y;
                int xl = (int)x;
                int yh, xh; float ly, lx;
                if (yl >= HH - 1) { yl = HH - 1; yh = HH - 1; ly = 0.f; }
                else              { yh = yl + 1; ly = y - (float)yl; }
                if (xl >= WW - 1) { xl = WW - 1; xh = WW - 1; lx = 0.f; }
                else              { xh = xl + 1; lx = x - (float)xl; }

                const float vsc = valid ? 0.25f : 0.0f;  // folds the /4 mean
                const float hy = 1.f - ly, hx = 1.f - lx;
                w[ix * 4 + 0] = hy * hx * vsc;
                w[ix * 4 + 1] = hy * lx * vsc;
                w[ix * 4 + 2] = ly * hx * vsc;
                w[ix * 4 + 3] = ly * lx * vsc;

                const int rl = yl * WW, rh2 = yh * WW;
                idx[ix * 4 + 0] = (rl  + xl) << 6;   // * (CCH/4)
                idx[ix * 4 + 1] = (rl  + xh) << 6;
                idx[ix * 4 + 2] = (rh2 + xl) << 6;
                idx[ix * 4 + 3] = (rh2 + xh) << 6;
            }

            float4 v[8];
#pragma unroll
            for (int i = 0; i < 8; ++i) v[i] = __ldg(feat + idx[i]);
#pragma unroll
            for (int i = 0; i < 8; ++i) {
                a0 = fmaf(w[i], v[i].x, a0);
                a1 = fmaf(w[i], v[i].y, a1);
                a2 = fmaf(w[i], v[i].z, a2);
                a3 = fmaf(w[i], v[i].w, a3);
            }
        }

        const int cb = cgrp * 4;
        s_out[(cb + 0) * NBINS + bin] = a0;
        s_out[(cb + 1) * NBINS + bin] = a1;
        s_out[(cb + 2) * NBINS + bin] = a2;
        s_out[(cb + 3) * NBINS + bin] = a3;
    }

    __syncthreads();
    float4* o4 = (float4*)(out + (size_t)roi * (CCH * NBINS));
    const float4* s4 = (const float4*)s_out;
#pragma unroll 4
    for (int i = tid; i < (CCH * NBINS) / 4; i += 512) {
        o4[i] = s4[i];
    }
}

extern "C" void kernel_launch(void* const* d_in, const int* in_sizes, int n_in,
                              void* d_out, int out_size)
{
    const float* feat = (const float*)d_in[0];
    const float* rois = (const float*)d_in[1];
    if (in_sizes[0] == NROIS * 6) {
        rois = (const float*)d_in[0];
        feat = (const float*)d_in[1];
    }
    float* out = (float*)d_out;

    cudaFuncSetAttribute(roialign_rot_kernel,
                         cudaFuncAttributeMaxDynamicSharedMemorySize,
                         CCH * NBINS * (int)sizeof(float));

    dim3 tg((HH * WW) / 128, CCH / 32, N_IMG);
    nchw_to_nhwc_kernel<<<tg, 256>>>(feat);

    roialign_rot_kernel<<<NROIS, 512, CCH * NBINS * (int)sizeof(float)>>>(rois, out);
}